// round 2
// baseline (speedup 1.0000x reference)
#include <cuda_runtime.h>
#include <cuda_bf16.h>

#define N_NODES 100000
#define N_EDGES 1600000
#define D 128
#define ALPHA 0.5f
#define TILE_NODES 32
#define N_TILES (N_NODES / TILE_NODES)     // 3125 exact
#define WPAD 132                            // weight row stride (words), 16B aligned, conflict-free
#define SCAN_B 1024
#define SCAN_NB ((N_NODES + SCAN_B - 1) / SCAN_B)   // 98

// -------- static device scratch --------
__device__ float g_y_src[(size_t)N_NODES * D];   // dinv_in[n] * (x @ (a*Ws)^T)[n]
__device__ float g_y_dst[(size_t)N_NODES * D];   // dinv_out[n] * (x @ ((1-a)*Wd)^T)[n]
__device__ int   g_cnt_row[N_NODES], g_cnt_col[N_NODES];
__device__ int   g_off_row[N_NODES], g_off_col[N_NODES];
__device__ int   g_cur_row[N_NODES], g_cur_col[N_NODES];
__device__ int   g_part_row[SCAN_NB], g_part_col[SCAN_NB];
__device__ float g_dinv_out[N_NODES], g_dinv_in[N_NODES];
__device__ int   g_sorted_col[N_EDGES];   // edges sorted by row; stores col
__device__ int   g_sorted_row[N_EDGES];   // edges sorted by col; stores row
__device__ int   g_is64;

__device__ __forceinline__ int ldidx(const void* p, long long i, int is64) {
  if (is64) return (int)((const long long*)p)[i];
  return ((const int*)p)[i];
}

__device__ __forceinline__ unsigned long long ffma2(
    unsigned long long a, unsigned long long b, unsigned long long c) {
  unsigned long long d;
  asm("fma.rn.f32x2 %0, %1, %2, %3;" : "=l"(d) : "l"(a), "l"(b), "l"(c));
  return d;
}
__device__ __forceinline__ float unpack_sum(unsigned long long a) {
  return __uint_as_float((unsigned)a) + __uint_as_float((unsigned)(a >> 32));
}

// -------- 1: zero histograms + detect index dtype --------
__global__ void k_prep(const void* ei) {
  long long i = (long long)blockIdx.x * blockDim.x + threadIdx.x;
  if (i == 0) {
    const long long* p = (const long long*)ei;
    int ok = 1;
#pragma unroll
    for (int j = 0; j < 16; j++) {
      long long v = p[j];
      if (v < 0 || v >= N_NODES) ok = 0;
    }
    g_is64 = ok;
  }
  if (i < N_NODES) { g_cnt_row[i] = 0; g_cnt_col[i] = 0; }
}

// -------- 2: degree histograms --------
__global__ void k_hist(const void* ei) {
  long long e = (long long)blockIdx.x * blockDim.x + threadIdx.x;
  if (e >= N_EDGES) return;
  int is64 = g_is64;
  int r = ldidx(ei, e, is64);
  int c = ldidx(ei, (long long)N_EDGES + e, is64);
  atomicAdd(&g_cnt_row[r], 1);
  atomicAdd(&g_cnt_col[c], 1);
}

// -------- 3: blockwise exclusive scan of both histograms --------
__global__ void k_scan_blocks() {
  __shared__ int sh[SCAN_B];
  int b = blockIdx.x, t = threadIdx.x;
  int gi = b * SCAN_B + t;

  int v = (gi < N_NODES) ? g_cnt_row[gi] : 0;
  sh[t] = v; __syncthreads();
  for (int o = 1; o < SCAN_B; o <<= 1) {
    int x = (t >= o) ? sh[t - o] : 0;
    __syncthreads(); sh[t] += x; __syncthreads();
  }
  if (gi < N_NODES) g_off_row[gi] = sh[t] - v;
  if (t == SCAN_B - 1) g_part_row[b] = sh[t];
  __syncthreads();

  v = (gi < N_NODES) ? g_cnt_col[gi] : 0;
  sh[t] = v; __syncthreads();
  for (int o = 1; o < SCAN_B; o <<= 1) {
    int x = (t >= o) ? sh[t - o] : 0;
    __syncthreads(); sh[t] += x; __syncthreads();
  }
  if (gi < N_NODES) g_off_col[gi] = sh[t] - v;
  if (t == SCAN_B - 1) g_part_col[b] = sh[t];
}

// -------- 4: scan the 98 block totals --------
__global__ void k_scan_tops() {
  __shared__ int sh[128];
  int t = threadIdx.x;
  int v = (t < SCAN_NB) ? g_part_row[t] : 0;
  sh[t] = v; __syncthreads();
  for (int o = 1; o < 128; o <<= 1) {
    int x = (t >= o) ? sh[t - o] : 0;
    __syncthreads(); sh[t] += x; __syncthreads();
  }
  if (t < SCAN_NB) g_part_row[t] = sh[t] - v;
  __syncthreads();
  v = (t < SCAN_NB) ? g_part_col[t] : 0;
  sh[t] = v; __syncthreads();
  for (int o = 1; o < 128; o <<= 1) {
    int x = (t >= o) ? sh[t - o] : 0;
    __syncthreads(); sh[t] += x; __syncthreads();
  }
  if (t < SCAN_NB) g_part_col[t] = sh[t] - v;
}

// -------- 5: finalize offsets, init cursors, compute dinv --------
__global__ void k_scan_add() {
  int b = blockIdx.x, t = threadIdx.x;
  int gi = b * SCAN_B + t;
  if (gi >= N_NODES) return;
  int orow = g_off_row[gi] + g_part_row[b];
  int ocol = g_off_col[gi] + g_part_col[b];
  g_off_row[gi] = orow; g_cur_row[gi] = orow;
  g_off_col[gi] = ocol; g_cur_col[gi] = ocol;
  int cr = g_cnt_row[gi], cc = g_cnt_col[gi];
  g_dinv_out[gi] = cr > 0 ? rsqrtf((float)cr) : 0.f;
  g_dinv_in[gi]  = cc > 0 ? rsqrtf((float)cc) : 0.f;
}

// -------- 6: build CSR (counting-sort scatter) --------
__global__ void k_build(const void* ei) {
  long long e = (long long)blockIdx.x * blockDim.x + threadIdx.x;
  if (e >= N_EDGES) return;
  int is64 = g_is64;
  int r = ldidx(ei, e, is64);
  int c = ldidx(ei, (long long)N_EDGES + e, is64);
  int p = atomicAdd(&g_cur_row[r], 1);
  g_sorted_col[p] = c;
  int q = atomicAdd(&g_cur_col[c], 1);
  g_sorted_row[q] = r;
}

// -------- 7: transform with packed f32x2 FMAs; pre-scale by dinv --------
__global__ void __launch_bounds__(256, 1) k_transform(
    const float* __restrict__ x,
    const float* __restrict__ W_src,
    const float* __restrict__ W_dst) {
  extern __shared__ float smem[];
  float* Ws = smem;                 // [128][WPAD], natural [d][k], scaled by ALPHA
  float* Wd = Ws + D * WPAD;        // scaled by 1-ALPHA
  float* xs = Wd + D * WPAD;        // [32 nodes][128]

  int tid = threadIdx.x;
  for (int idx = tid; idx < D * D; idx += 256) {
    int d = idx >> 7, k = idx & 127;
    Ws[d * WPAD + k] = ALPHA * W_src[idx];
    Wd[d * WPAD + k] = (1.f - ALPHA) * W_dst[idx];
  }
  int d = tid & 127;
  int half = tid >> 7;
  __syncthreads();

  const ulonglong2* wsp = (const ulonglong2*)(Ws + d * WPAD);
  const ulonglong2* wdp = (const ulonglong2*)(Wd + d * WPAD);

  for (int tile = blockIdx.x; tile < N_TILES; tile += gridDim.x) {
    long long base = (long long)tile * TILE_NODES;
    for (int idx = tid; idx < TILE_NODES * D; idx += 256)
      xs[idx] = x[base * D + idx];
    __syncthreads();

    unsigned long long acc_s[16], acc_d[16];
#pragma unroll
    for (int i = 0; i < 16; i++) { acc_s[i] = 0ull; acc_d[i] = 0ull; }

    const ulonglong2* xrow = (const ulonglong2*)(xs + (half * 16) * D);
#pragma unroll 2
    for (int kg = 0; kg < 32; kg++) {          // 4 k per group
      ulonglong2 ws = wsp[kg];                 // (w[k0],w[k1]) , (w[k2],w[k3])
      ulonglong2 wd = wdp[kg];
#pragma unroll
      for (int i = 0; i < 16; i++) {
        ulonglong2 xv = xrow[i * 32 + kg];     // broadcast LDS.128
        acc_s[i] = ffma2(xv.x, ws.x, acc_s[i]);
        acc_s[i] = ffma2(xv.y, ws.y, acc_s[i]);
        acc_d[i] = ffma2(xv.x, wd.x, acc_d[i]);
        acc_d[i] = ffma2(xv.y, wd.y, acc_d[i]);
      }
    }

#pragma unroll
    for (int i = 0; i < 16; i++) {
      long long node = base + half * 16 + i;
      float di = g_dinv_in[node];
      float dout = g_dinv_out[node];
      g_y_src[node * D + d] = di   * unpack_sum(acc_s[i]);
      g_y_dst[node * D + d] = dout * unpack_sum(acc_d[i]);
    }
    __syncthreads();
  }
}

// -------- 8: gather — warp per node, both directions, single out write --------
__global__ void k_gather(float* __restrict__ out,
                         const float* __restrict__ b_src,
                         const float* __restrict__ b_dst) {
  int lane = threadIdx.x & 31;
  int node = (blockIdx.x * blockDim.x + threadIdx.x) >> 5;
  if (node >= N_NODES) return;

  float4 accf = make_float4(0.f, 0.f, 0.f, 0.f);
  float4 accb = make_float4(0.f, 0.f, 0.f, 0.f);

  // forward: edges node -> c, sum y_src'[c]
  {
    int s = g_off_row[node], cnt = g_cnt_row[node];
    for (int bse = 0; bse < cnt; bse += 32) {
      int n = min(32, cnt - bse);
      int c = (lane < n) ? g_sorted_col[s + bse + lane] : 0;
      for (int j = 0; j < n; j++) {
        int cc = __shfl_sync(0xffffffffu, c, j);
        float4 v = ((const float4*)(g_y_src + (long long)cc * D))[lane];
        accf.x += v.x; accf.y += v.y; accf.z += v.z; accf.w += v.w;
      }
    }
  }
  // backward: edges r -> node, sum y_dst'[r]
  {
    int s = g_off_col[node], cnt = g_cnt_col[node];
    for (int bse = 0; bse < cnt; bse += 32) {
      int n = min(32, cnt - bse);
      int r = (lane < n) ? g_sorted_row[s + bse + lane] : 0;
      for (int j = 0; j < n; j++) {
        int rr = __shfl_sync(0xffffffffu, r, j);
        float4 v = ((const float4*)(g_y_dst + (long long)rr * D))[lane];
        accb.x += v.x; accb.y += v.y; accb.z += v.z; accb.w += v.w;
      }
    }
  }

  float dout = g_dinv_out[node];
  float di   = g_dinv_in[node];
  float4 o;
  int bidx = lane * 4;
  o.x = ALPHA * b_src[bidx+0] + (1.f - ALPHA) * b_dst[bidx+0] + dout * accf.x + di * accb.x;
  o.y = ALPHA * b_src[bidx+1] + (1.f - ALPHA) * b_dst[bidx+1] + dout * accf.y + di * accb.y;
  o.z = ALPHA * b_src[bidx+2] + (1.f - ALPHA) * b_dst[bidx+2] + dout * accf.z + di * accb.z;
  o.w = ALPHA * b_src[bidx+3] + (1.f - ALPHA) * b_dst[bidx+3] + dout * accf.w + di * accb.w;
  ((float4*)(out + (long long)node * D))[lane] = o;
}

// -------- launch --------
extern "C" void kernel_launch(void* const* d_in, const int* in_sizes, int n_in,
                              void* d_out, int out_size) {
  const float* x     = (const float*)d_in[0];
  const void*  ei    = d_in[1];
  const float* W_src = (const float*)d_in[2];
  const float* b_src = (const float*)d_in[3];
  const float* W_dst = (const float*)d_in[4];
  const float* b_dst = (const float*)d_in[5];
  float* out = (float*)d_out;

  k_prep<<<(N_NODES + 255) / 256, 256>>>(ei);
  k_hist<<<(N_EDGES + 255) / 256, 256>>>(ei);
  k_scan_blocks<<<SCAN_NB, SCAN_B>>>();
  k_scan_tops<<<1, 128>>>();
  k_scan_add<<<SCAN_NB, SCAN_B>>>();
  k_build<<<(N_EDGES + 255) / 256, 256>>>(ei);

  size_t smem_bytes = (size_t)(2 * D * WPAD + TILE_NODES * D) * sizeof(float);
  cudaFuncSetAttribute(k_transform, cudaFuncAttributeMaxDynamicSharedMemorySize,
                       (int)smem_bytes);
  k_transform<<<152, 256, smem_bytes>>>(x, W_src, W_dst);

  k_gather<<<(N_NODES * 32 + 255) / 256, 256>>>(out, b_src, b_dst);
}